// round 8
// baseline (speedup 1.0000x reference)
#include <cuda_runtime.h>

// Problem constants (fixed shapes from reference setup_inputs)
#define BATCH 4
#define NPTS  8192
#define CH    32      // input channels
#define KNN   16      // neighbors
#define LDIM  64      // hidden (dense)
#define ODIM  128     // output channels
#define TILE  128     // candidate tile (== TPB)
#define TPB   128     // threads per block = queries per block

// ---------------- device scratch (no allocs allowed) ----------------
__device__ float g_Wf[CH * ODIM];    // fused W_lin @ W_conv  [32,128]
__device__ float g_bf[ODIM];         // fused bias            [128]
__device__ float g_sq[BATCH * NPTS]; // per-point squared norms

// ---------------- packed f32x2 helpers ----------------
__device__ __forceinline__ void fma2(unsigned long long& acc,
                                     unsigned long long a,
                                     unsigned long long b) {
    asm("fma.rn.f32x2 %0, %1, %2, %3;" : "=l"(acc) : "l"(a), "l"(b), "l"(acc));
}
__device__ __forceinline__ float hsum2(unsigned long long v) {
    float lo, hi;
    asm("mov.b64 {%0, %1}, %2;" : "=f"(lo), "=f"(hi) : "l"(v));
    return lo + hi;
}

// ---------------- prep: fuse the two linear layers ----------------
// out = relu(pooled @ (W_lin@W_conv) + (b_lin@W_conv + b_conv))
__global__ void prep_weights(const float* __restrict__ W_lin,
                             const float* __restrict__ b_lin,
                             const float* __restrict__ W_conv,
                             const float* __restrict__ b_conv) {
    int o = threadIdx.x;             // 128 threads, one output channel each
    float bb = b_conv[o];
    for (int l = 0; l < LDIM; ++l) bb += b_lin[l] * W_conv[l * ODIM + o];
    g_bf[o] = bb;
    for (int c = 0; c < CH; ++c) {
        float acc = 0.f;
        for (int l = 0; l < LDIM; ++l)
            acc += W_lin[c * LDIM + l] * W_conv[l * ODIM + o];
        g_Wf[c * ODIM + o] = acc;
    }
}

// ---------------- prep: squared norms ----------------
__global__ void prep_sq(const float* __restrict__ x) {
    int p = blockIdx.x * blockDim.x + threadIdx.x;   // 0 .. BATCH*NPTS-1
    const float4* xp = reinterpret_cast<const float4*>(x + (size_t)p * CH);
    float s = 0.f;
#pragma unroll
    for (int i = 0; i < CH / 4; ++i) {
        float4 v = xp[i];
        s += v.x * v.x + v.y * v.y + v.z * v.z + v.w * v.w;
    }
    g_sq[p] = s;
}

// ---------------- main fused kernel ----------------
// One thread = one query point. Exact-fp32 KNN score: sq_j - 2*dot(x_i,x_j)
// (dropping the per-query constant sq_i keeps the ordering identical).
__global__ __launch_bounds__(TPB)
void knn_pool_mlp(const float* __restrict__ x, float* __restrict__ out) {
    __shared__ float4 s_cand[TILE * (CH / 4)];   // 16 KB candidate tile
    __shared__ float  s_sq[TILE];
    __shared__ float  s_Wf[CH * ODIM];           // 16 KB fused weights
    __shared__ float  s_bf[ODIM];

    const int blocks_per_batch = NPTS / TPB;     // 64
    const int b  = blockIdx.x / blocks_per_batch;
    const int q0 = (blockIdx.x % blocks_per_batch) * TPB;
    const int t  = threadIdx.x;
    const int q  = q0 + t;
    const float* xb = x + (size_t)b * NPTS * CH;

    // stage fused weights (once per block)
#pragma unroll
    for (int i = t; i < CH * ODIM; i += TPB) s_Wf[i] = g_Wf[i];
    s_bf[t] = g_bf[t];                            // ODIM == TPB

    // load query features as 16 packed f32x2 registers
    unsigned long long q2[CH / 2];
    {
        const ulonglong2* qp =
            reinterpret_cast<const ulonglong2*>(xb + (size_t)q * CH);
#pragma unroll
        for (int i = 0; i < CH / 4; ++i) {
            ulonglong2 v = qp[i];
            q2[2 * i]     = v.x;
            q2[2 * i + 1] = v.y;
        }
    }

    // top-16 smallest scores, sorted ascending, in registers
    float best_d[KNN];
    int   best_i[KNN];
#pragma unroll
    for (int r = 0; r < KNN; ++r) { best_d[r] = INFINITY; best_i[r] = -1; }
    float worst = INFINITY;

    const float* sqb = g_sq + b * NPTS;

    for (int j0 = 0; j0 < NPTS; j0 += TILE) {
        __syncthreads();   // previous tile fully consumed (also covers Wf load)
        {
            const float4* src =
                reinterpret_cast<const float4*>(xb + (size_t)j0 * CH);
#pragma unroll
            for (int i = 0; i < TILE * (CH / 4) / TPB; ++i)
                s_cand[t + i * TPB] = src[t + i * TPB];
            s_sq[t] = sqb[j0 + t];                // TILE == TPB
        }
        __syncthreads();

        for (int jj = 0; jj < TILE; ++jj) {
            const ulonglong2* cp =
                reinterpret_cast<const ulonglong2*>(&s_cand[jj * (CH / 4)]);
            unsigned long long a0 = 0ull, a1 = 0ull;   // packed (0,0)
#pragma unroll
            for (int i = 0; i < CH / 4; ++i) {
                ulonglong2 v = cp[i];                   // broadcast LDS.128
                fma2(a0, q2[2 * i],     v.x);
                fma2(a1, q2[2 * i + 1], v.y);
            }
            float dot   = hsum2(a0) + hsum2(a1);
            float score = fmaf(-2.f, dot, s_sq[jj]);

            if (score < worst) {                        // rare path (~1-2%)
                float d = score;
                int   id = j0 + jj;
#pragma unroll
                for (int r = 0; r < KNN; ++r) {
                    float od = best_d[r];
                    int   oi = best_i[r];
                    bool  sw = d < od;                  // strict: ties keep lower idx
                    best_d[r] = sw ? d  : od;
                    best_i[r] = sw ? id : oi;
                    d  = sw ? od : d;
                    id = sw ? oi : id;
                }
                worst = best_d[KNN - 1];
            }
        }
    }

    // gather neighbor features + max pool (L2-resident: 1 MB/batch)
    float pooled[CH];
#pragma unroll
    for (int c = 0; c < CH; ++c) pooled[c] = -INFINITY;
#pragma unroll
    for (int r = 0; r < KNN; ++r) {
        const float4* np =
            reinterpret_cast<const float4*>(xb + (size_t)best_i[r] * CH);
#pragma unroll
        for (int i = 0; i < CH / 4; ++i) {
            float4 v = __ldg(np + i);
            pooled[4 * i + 0] = fmaxf(pooled[4 * i + 0], v.x);
            pooled[4 * i + 1] = fmaxf(pooled[4 * i + 1], v.y);
            pooled[4 * i + 2] = fmaxf(pooled[4 * i + 2], v.z);
            pooled[4 * i + 3] = fmaxf(pooled[4 * i + 3], v.w);
        }
    }

    // fused MLP: out = relu(pooled @ Wf + bf), Wf broadcast from smem
    float* outp = out + ((size_t)b * NPTS + q) * ODIM;
#pragma unroll
    for (int o0 = 0; o0 < ODIM; o0 += 32) {
        float acc[32];
#pragma unroll
        for (int oi = 0; oi < 32; ++oi) acc[oi] = s_bf[o0 + oi];
#pragma unroll
        for (int c = 0; c < CH; ++c) {
            float p = pooled[c];
            const float4* wrow =
                reinterpret_cast<const float4*>(&s_Wf[c * ODIM + o0]);
#pragma unroll
            for (int i = 0; i < 8; ++i) {
                float4 w = wrow[i];
                acc[4 * i + 0] = fmaf(p, w.x, acc[4 * i + 0]);
                acc[4 * i + 1] = fmaf(p, w.y, acc[4 * i + 1]);
                acc[4 * i + 2] = fmaf(p, w.z, acc[4 * i + 2]);
                acc[4 * i + 3] = fmaf(p, w.w, acc[4 * i + 3]);
            }
        }
        float4* op = reinterpret_cast<float4*>(outp + o0);
#pragma unroll
        for (int i = 0; i < 8; ++i) {
            float4 v;
            v.x = fmaxf(acc[4 * i + 0], 0.f);
            v.y = fmaxf(acc[4 * i + 1], 0.f);
            v.z = fmaxf(acc[4 * i + 2], 0.f);
            v.w = fmaxf(acc[4 * i + 3], 0.f);
            op[i] = v;
        }
    }
}

extern "C" void kernel_launch(void* const* d_in, const int* in_sizes, int n_in,
                              void* d_out, int out_size) {
    const float* x      = (const float*)d_in[0];  // [B,N,C]
    const float* W_lin  = (const float*)d_in[1];  // [C,L]
    const float* b_lin  = (const float*)d_in[2];  // [L]
    const float* W_conv = (const float*)d_in[3];  // [L,O]
    const float* b_conv = (const float*)d_in[4];  // [O]
    float* out = (float*)d_out;                   // [B,N,O]

    (void)in_sizes; (void)n_in; (void)out_size;

    prep_weights<<<1, ODIM>>>(W_lin, b_lin, W_conv, b_conv);
    prep_sq<<<(BATCH * NPTS) / 256, 256>>>(x);
    knn_pool_mlp<<<BATCH * (NPTS / TPB), TPB>>>(x, out);
}

// round 9
// speedup vs baseline: 1.0010x; 1.0010x over previous
#include <cuda_runtime.h>

// Problem constants (fixed shapes from reference setup_inputs)
#define BATCH 4
#define NPTS  8192
#define CH    32      // input channels
#define KNN   16      // neighbors
#define LDIM  64      // hidden (dense)
#define ODIM  128     // output channels
#define TILE  128     // candidate tile (== TPB)
#define TPB   128     // threads per block = queries per block

// ---------------- device scratch (no allocs allowed) ----------------
__device__ float g_Wf[CH * ODIM];    // fused W_lin @ W_conv  [32,128]
__device__ float g_bf[ODIM];         // fused bias            [128]
__device__ float g_sq[BATCH * NPTS]; // per-point squared norms

// ---------------- packed f32x2 helpers ----------------
__device__ __forceinline__ void fma2(unsigned long long& acc,
                                     unsigned long long a,
                                     unsigned long long b) {
    asm("fma.rn.f32x2 %0, %1, %2, %3;" : "=l"(acc) : "l"(a), "l"(b), "l"(acc));
}
__device__ __forceinline__ float hsum2(unsigned long long v) {
    float lo, hi;
    asm("mov.b64 {%0, %1}, %2;" : "=f"(lo), "=f"(hi) : "l"(v));
    return lo + hi;
}

// ---------------- prep: fuse the two linear layers ----------------
// out = relu(pooled @ (W_lin@W_conv) + (b_lin@W_conv + b_conv))
__global__ void prep_weights(const float* __restrict__ W_lin,
                             const float* __restrict__ b_lin,
                             const float* __restrict__ W_conv,
                             const float* __restrict__ b_conv) {
    int o = threadIdx.x;             // 128 threads, one output channel each
    float bb = b_conv[o];
    for (int l = 0; l < LDIM; ++l) bb += b_lin[l] * W_conv[l * ODIM + o];
    g_bf[o] = bb;
    for (int c = 0; c < CH; ++c) {
        float acc = 0.f;
        for (int l = 0; l < LDIM; ++l)
            acc += W_lin[c * LDIM + l] * W_conv[l * ODIM + o];
        g_Wf[c * ODIM + o] = acc;
    }
}

// ---------------- prep: squared norms ----------------
__global__ void prep_sq(const float* __restrict__ x) {
    int p = blockIdx.x * blockDim.x + threadIdx.x;   // 0 .. BATCH*NPTS-1
    const float4* xp = reinterpret_cast<const float4*>(x + (size_t)p * CH);
    float s = 0.f;
#pragma unroll
    for (int i = 0; i < CH / 4; ++i) {
        float4 v = xp[i];
        s += v.x * v.x + v.y * v.y + v.z * v.z + v.w * v.w;
    }
    g_sq[p] = s;
}

// ---------------- main fused kernel ----------------
// One thread = one query point. Exact-fp32 KNN score: sq_j - 2*dot(x_i,x_j)
// (dropping the per-query constant sq_i keeps the ordering identical).
__global__ __launch_bounds__(TPB)
void knn_pool_mlp(const float* __restrict__ x, float* __restrict__ out) {
    __shared__ float4 s_cand[TILE * (CH / 4)];   // 16 KB candidate tile
    __shared__ float  s_sq[TILE];
    __shared__ float  s_Wf[CH * ODIM];           // 16 KB fused weights
    __shared__ float  s_bf[ODIM];

    const int blocks_per_batch = NPTS / TPB;     // 64
    const int b  = blockIdx.x / blocks_per_batch;
    const int q0 = (blockIdx.x % blocks_per_batch) * TPB;
    const int t  = threadIdx.x;
    const int q  = q0 + t;
    const float* xb = x + (size_t)b * NPTS * CH;

    // stage fused weights (once per block)
#pragma unroll
    for (int i = t; i < CH * ODIM; i += TPB) s_Wf[i] = g_Wf[i];
    s_bf[t] = g_bf[t];                            // ODIM == TPB

    // load query features as 16 packed f32x2 registers
    unsigned long long q2[CH / 2];
    {
        const ulonglong2* qp =
            reinterpret_cast<const ulonglong2*>(xb + (size_t)q * CH);
#pragma unroll
        for (int i = 0; i < CH / 4; ++i) {
            ulonglong2 v = qp[i];
            q2[2 * i]     = v.x;
            q2[2 * i + 1] = v.y;
        }
    }

    // top-16 smallest scores, sorted ascending, in registers
    float best_d[KNN];
    int   best_i[KNN];
#pragma unroll
    for (int r = 0; r < KNN; ++r) { best_d[r] = INFINITY; best_i[r] = -1; }
    float worst = INFINITY;

    const float* sqb = g_sq + b * NPTS;

    for (int j0 = 0; j0 < NPTS; j0 += TILE) {
        __syncthreads();   // previous tile fully consumed (also covers Wf load)
        {
            const float4* src =
                reinterpret_cast<const float4*>(xb + (size_t)j0 * CH);
#pragma unroll
            for (int i = 0; i < TILE * (CH / 4) / TPB; ++i)
                s_cand[t + i * TPB] = src[t + i * TPB];
            s_sq[t] = sqb[j0 + t];                // TILE == TPB
        }
        __syncthreads();

        for (int jj = 0; jj < TILE; ++jj) {
            const ulonglong2* cp =
                reinterpret_cast<const ulonglong2*>(&s_cand[jj * (CH / 4)]);
            unsigned long long a0 = 0ull, a1 = 0ull;   // packed (0,0)
#pragma unroll
            for (int i = 0; i < CH / 4; ++i) {
                ulonglong2 v = cp[i];                   // broadcast LDS.128
                fma2(a0, q2[2 * i],     v.x);
                fma2(a1, q2[2 * i + 1], v.y);
            }
            float dot   = hsum2(a0) + hsum2(a1);
            float score = fmaf(-2.f, dot, s_sq[jj]);

            if (score < worst) {                        // rare path (~1-2%)
                float d = score;
                int   id = j0 + jj;
#pragma unroll
                for (int r = 0; r < KNN; ++r) {
                    float od = best_d[r];
                    int   oi = best_i[r];
                    bool  sw = d < od;                  // strict: ties keep lower idx
                    best_d[r] = sw ? d  : od;
                    best_i[r] = sw ? id : oi;
                    d  = sw ? od : d;
                    id = sw ? oi : id;
                }
                worst = best_d[KNN - 1];
            }
        }
    }

    // gather neighbor features + max pool (L2-resident: 1 MB/batch)
    float pooled[CH];
#pragma unroll
    for (int c = 0; c < CH; ++c) pooled[c] = -INFINITY;
#pragma unroll
    for (int r = 0; r < KNN; ++r) {
        const float4* np =
            reinterpret_cast<const float4*>(xb + (size_t)best_i[r] * CH);
#pragma unroll
        for (int i = 0; i < CH / 4; ++i) {
            float4 v = __ldg(np + i);
            pooled[4 * i + 0] = fmaxf(pooled[4 * i + 0], v.x);
            pooled[4 * i + 1] = fmaxf(pooled[4 * i + 1], v.y);
            pooled[4 * i + 2] = fmaxf(pooled[4 * i + 2], v.z);
            pooled[4 * i + 3] = fmaxf(pooled[4 * i + 3], v.w);
        }
    }

    // fused MLP: out = relu(pooled @ Wf + bf), Wf broadcast from smem
    float* outp = out + ((size_t)b * NPTS + q) * ODIM;
#pragma unroll
    for (int o0 = 0; o0 < ODIM; o0 += 32) {
        float acc[32];
#pragma unroll
        for (int oi = 0; oi < 32; ++oi) acc[oi] = s_bf[o0 + oi];
#pragma unroll
        for (int c = 0; c < CH; ++c) {
            float p = pooled[c];
            const float4* wrow =
                reinterpret_cast<const float4*>(&s_Wf[c * ODIM + o0]);
#pragma unroll
            for (int i = 0; i < 8; ++i) {
                float4 w = wrow[i];
                acc[4 * i + 0] = fmaf(p, w.x, acc[4 * i + 0]);
                acc[4 * i + 1] = fmaf(p, w.y, acc[4 * i + 1]);
                acc[4 * i + 2] = fmaf(p, w.z, acc[4 * i + 2]);
                acc[4 * i + 3] = fmaf(p, w.w, acc[4 * i + 3]);
            }
        }
        float4* op = reinterpret_cast<float4*>(outp + o0);
#pragma unroll
        for (int i = 0; i < 8; ++i) {
            float4 v;
            v.x = fmaxf(acc[4 * i + 0], 0.f);
            v.y = fmaxf(acc[4 * i + 1], 0.f);
            v.z = fmaxf(acc[4 * i + 2], 0.f);
            v.w = fmaxf(acc[4 * i + 3], 0.f);
            op[i] = v;
        }
    }
}

extern "C" void kernel_launch(void* const* d_in, const int* in_sizes, int n_in,
                              void* d_out, int out_size) {
    const float* x      = (const float*)d_in[0];  // [B,N,C]
    const float* W_lin  = (const float*)d_in[1];  // [C,L]
    const float* b_lin  = (const float*)d_in[2];  // [L]
    const float* W_conv = (const float*)d_in[3];  // [L,O]
    const float* b_conv = (const float*)d_in[4];  // [O]
    float* out = (float*)d_out;                   // [B,N,O]

    (void)in_sizes; (void)n_in; (void)out_size;

    prep_weights<<<1, ODIM>>>(W_lin, b_lin, W_conv, b_conv);
    prep_sq<<<(BATCH * NPTS) / 256, 256>>>(x);
    knn_pool_mlp<<<BATCH * (NPTS / TPB), TPB>>>(x, out);
}